// round 10
// baseline (speedup 1.0000x reference)
#include <cuda_runtime.h>
#include <cuda_fp16.h>
#include <math.h>
#include <stdint.h>

// Problem constants (fixed shapes: B=4096, D=256, T=0.5)
#define NB     4096
#define D      256
#define N2     8192
#define BM     128
#define BN     128
#define BKB    64            // k-bytes per chunk (fp8)
#define NKC    (D / BKB)     // 4 k-chunks
#define NCT    64            // partial slots per row
#define NRT    (N2 / BM)     // 64 row tiles
#define NTRI   (NRT * (NRT + 1) / 2)   // 2080 upper-tri tiles
#define PITCH  80            // smem row pitch bytes (64B data + 16B pad)
#define STAGE_BYTES (2 * BM * PITCH)   // A + B tile = 20480
#define NSTAGE 4
#define REDR_OFF (NSTAGE * STAGE_BYTES)          // 81920: red_row[128][4]
#define REDC_OFF (REDR_OFF + BM * 4 * 4)         // red_col[128][2]
#define SMEM_BYTES (REDC_OFF + BM * 2 * 4)
#define FBLK   64            // kfinal blocks (128 rows each)

// Scratch (static device globals; no allocation allowed)
__device__ unsigned char g_z8[N2 * D];  // normalized rows, fp8 e4m3
__device__ float g_partial[N2 * NCT];   // per-row exp-sum partial per slot
__device__ float g_pos[N2];             // sim[k, k +- NB]
__device__ float g_blocksum[FBLK];      // per-block loss partial
__device__ int   g_ctr;                 // kfinal completion counter

// ---------------------------------------------------------------------------
__device__ __forceinline__ uint32_t smem_u32(const void* p) {
    uint32_t a;
    asm("{ .reg .u64 t; cvta.to.shared.u64 t, %1; cvt.u32.u64 %0, t; }"
        : "=r"(a) : "l"(p));
    return a;
}
__device__ __forceinline__ void cp_async16(uint32_t smem, const void* g) {
    asm volatile("cp.async.cg.shared.global [%0], [%1], 16;" :: "r"(smem), "l"(g));
}
#define CP_COMMIT() asm volatile("cp.async.commit_group;" ::: "memory")
#define CP_WAIT(n)  asm volatile("cp.async.wait_group %0;" :: "n"(n) : "memory")

__device__ __forceinline__ void ldsm4(uint32_t* r, uint32_t addr) {
    asm volatile("ldmatrix.sync.aligned.m8n8.x4.shared.b16 {%0,%1,%2,%3}, [%4];"
        : "=r"(r[0]), "=r"(r[1]), "=r"(r[2]), "=r"(r[3]) : "r"(addr));
}
// fp8 e4m3 MMA, m16n8k32, f32 accumulate
__device__ __forceinline__ void qmma16832(float* c, const uint32_t* a,
                                          const uint32_t* b) {
    asm volatile("mma.sync.aligned.m16n8k32.row.col.f32.e4m3.e4m3.f32 "
        "{%0,%1,%2,%3}, {%4,%5,%6,%7}, {%8,%9}, {%0,%1,%2,%3};"
        : "+f"(c[0]), "+f"(c[1]), "+f"(c[2]), "+f"(c[3])
        : "r"(a[0]), "r"(a[1]), "r"(a[2]), "r"(a[3]), "r"(b[0]), "r"(b[1]));
}
// pack two floats -> e4m3x2 (a -> upper byte, b -> lower byte)
__device__ __forceinline__ uint16_t pack_e4m3x2(float hi, float lo) {
    uint16_t r;
    asm("cvt.rn.satfinite.e4m3x2.f32 %0, %1, %2;" : "=h"(r) : "f"(hi), "f"(lo));
    return r;
}

// ---------------------------------------------------------------------------
// Kernel 1: L2-normalize rows of x_i / x_j (fp32 math) into fp8 g_z8.
// ---------------------------------------------------------------------------
__global__ __launch_bounds__(256) void knorm(const float* __restrict__ xi,
                                             const float* __restrict__ xj) {
    if (blockIdx.x == 0 && threadIdx.x == 0) g_ctr = 0;   // reset kfinal counter
    int warp = threadIdx.x >> 5;
    int lane = threadIdx.x & 31;
    int row  = blockIdx.x * 8 + warp;
    const float* src = (row < NB) ? (xi + (size_t)row * D)
                                  : (xj + (size_t)(row - NB) * D);
    float4 v0 = ((const float4*)src)[lane];
    float4 v1 = ((const float4*)src)[lane + 32];
    float ss = v0.x*v0.x + v0.y*v0.y + v0.z*v0.z + v0.w*v0.w
             + v1.x*v1.x + v1.y*v1.y + v1.z*v1.z + v1.w*v1.w;
#pragma unroll
    for (int off = 16; off > 0; off >>= 1)
        ss += __shfl_xor_sync(0xffffffffu, ss, off);
    float sc = 1.0f / fmaxf(sqrtf(ss), 1e-12f);
    uint32_t* dst = (uint32_t*)(g_z8 + (size_t)row * D);
    uint32_t w0 = (uint32_t)pack_e4m3x2(v0.y * sc, v0.x * sc)
                | ((uint32_t)pack_e4m3x2(v0.w * sc, v0.z * sc) << 16);
    uint32_t w1 = (uint32_t)pack_e4m3x2(v1.y * sc, v1.x * sc)
                | ((uint32_t)pack_e4m3x2(v1.w * sc, v1.z * sc) << 16);
    dst[lane]      = w0;
    dst[lane + 32] = w1;
}

// ---------------------------------------------------------------------------
// Stage loader: A(128x64B) + B(128x64B) fp8 tiles via cp.async.
// ---------------------------------------------------------------------------
__device__ __forceinline__ void load_stage(uint32_t sbase, int rb, int cb,
                                           int k0, int tid) {
#pragma unroll
    for (int i = 0; i < 4; i++) {          // 1024 16B segments / 256 threads
        int t = tid + i * 256;
        int row = t >> 2, seg = t & 3;
        int grow = (row < BM) ? (rb + row) : (cb + row - BM);
        cp_async16(sbase + (uint32_t)(row * PITCH + seg * 16),
                   g_z8 + (size_t)grow * D + k0 + seg * 16);
    }
}

// ---------------------------------------------------------------------------
// Kernel 2: fp8 QMMA sim-GEMM on UPPER-TRIANGULAR tiles only (symmetry).
// 128x128 CTA tile, 8 warps (2m x 4n), warp tile 64x32, m16n8k32 e4m3.
// ---------------------------------------------------------------------------
__global__ __launch_bounds__(256, 2) void kmain_qmma() {
    extern __shared__ char smem[];
    const uint32_t sb = smem_u32(smem);
    float* red_row = (float*)(smem + REDR_OFF);   // [128][4]
    float* red_col = (float*)(smem + REDC_OFF);   // [128][2]

    // Triangular decode: linear blockIdx -> (it, jt), it <= jt.
    int rem = blockIdx.x;
    int it = 0;
    while (rem >= NRT - it) { rem -= NRT - it; it++; }
    const int jt = it + rem;
    const bool offd = (jt > it);
    const bool haspos = (jt == it + NB / BM);

    const int tid = threadIdx.x;
    const int wid = tid >> 5, lid = tid & 31;
    const int wm = wid >> 2;                  // 0..1  (rows wm*64)
    const int wn = wid & 3;                   // 0..3  (cols wn*32)
    const int rb = it * BM;
    const int cb = jt * BN;

    float acc[4][4][4];
#pragma unroll
    for (int i = 0; i < 4; i++)
#pragma unroll
        for (int j = 0; j < 4; j++)
#pragma unroll
            for (int e = 0; e < 4; e++) acc[i][j][e] = 0.0f;

    // Prologue: fill 3 of 4 stages
    load_stage(sb + 0 * STAGE_BYTES, rb, cb, 0 * BKB, tid); CP_COMMIT();
    load_stage(sb + 1 * STAGE_BYTES, rb, cb, 1 * BKB, tid); CP_COMMIT();
    load_stage(sb + 2 * STAGE_BYTES, rb, cb, 2 * BKB, tid); CP_COMMIT();

    // byte-level fragment addressing (m16n8k32 = f16 pattern scaled x2)
    const int arow  = (lid & 7) + ((lid >> 3) & 1) * 8;
    const int akoff = (lid >> 4) * 16;
    const int bjrow = ((lid >> 4) & 1) * 8 + (lid & 7);
    const int bkoff = ((lid >> 3) & 1) * 16;

#pragma unroll
    for (int k = 0; k < NKC; k++) {
        if (k <= 1)      { CP_WAIT(2); }
        else if (k == 2) { CP_WAIT(1); }
        else             { CP_WAIT(0); }
        __syncthreads();
        if (k + 3 < NKC) {   // only k==0 for NKC=4
            load_stage(sb + ((k + 3) & 3) * STAGE_BYTES, rb, cb, (k + 3) * BKB, tid);
            CP_COMMIT();
        }
        const uint32_t aB = sb + (k & 3) * STAGE_BYTES;
        const uint32_t bB = aB + BM * PITCH;
#pragma unroll
        for (int kf = 0; kf < 2; kf++) {     // two k32 steps per 64B chunk
            uint32_t af[4][4], bf[4][2];
#pragma unroll
            for (int i = 0; i < 4; i++)
                ldsm4(af[i], aB + (uint32_t)((wm * 64 + i * 16 + arow) * PITCH
                                             + kf * 32 + akoff));
#pragma unroll
            for (int q = 0; q < 2; q++) {
                uint32_t br[4];
                ldsm4(br, bB + (uint32_t)((wn * 32 + q * 16 + bjrow) * PITCH
                                          + kf * 32 + bkoff));
                bf[q * 2 + 0][0] = br[0]; bf[q * 2 + 0][1] = br[1];
                bf[q * 2 + 1][0] = br[2]; bf[q * 2 + 1][1] = br[3];
            }
#pragma unroll
            for (int i = 0; i < 4; i++)
#pragma unroll
                for (int j = 0; j < 4; j++)
                    qmma16832(acc[i][j], af[i], bf[j]);
        }
    }

    // Fragment coords: row = wm*64 + i*16 + (lid>>2) + (e>=2)*8
    //                  col = wn*32 + j*8  + (lid&3)*2 + (e&1)
    const int r0 = lid >> 2;
    const int c0 = (lid & 3) * 2;

    // Pass 0: exp in place (+ pos capture, + self-diagonal mask on diag tiles)
#pragma unroll
    for (int i = 0; i < 4; i++)
#pragma unroll
        for (int j = 0; j < 4; j++)
#pragma unroll
            for (int e = 0; e < 4; e++) {
                const float v = acc[i][j][e];
                float ev = __expf(v * 2.0f);
                if (haspos) {
                    const int lm = wm * 64 + i * 16 + r0 + (e >> 1) * 8;
                    const int ln = wn * 32 + j * 8 + c0 + (e & 1);
                    if (ln == lm) { g_pos[rb + lm] = v; g_pos[cb + ln] = v; }
                }
                if (!offd) {
                    const int lm = wm * 64 + i * 16 + r0 + (e >> 1) * 8;
                    const int ln = wn * 32 + j * 8 + c0 + (e & 1);
                    if (ln == lm) ev = 0.0f;     // exclude self-similarity
                }
                acc[i][j][e] = ev;
            }

    // Pass 1: row sums -> red_row
    {
        float rsum[4][2];
#pragma unroll
        for (int i = 0; i < 4; i++) { rsum[i][0] = 0.0f; rsum[i][1] = 0.0f; }
#pragma unroll
        for (int i = 0; i < 4; i++)
#pragma unroll
            for (int j = 0; j < 4; j++) {
                rsum[i][0] += acc[i][j][0] + acc[i][j][1];
                rsum[i][1] += acc[i][j][2] + acc[i][j][3];
            }
#pragma unroll
        for (int i = 0; i < 4; i++)
#pragma unroll
            for (int h = 0; h < 2; h++) {
#pragma unroll
                for (int off = 1; off <= 2; off <<= 1)
                    rsum[i][h] += __shfl_xor_sync(0xffffffffu, rsum[i][h], off);
            }
        if ((lid & 3) == 0) {
#pragma unroll
            for (int i = 0; i < 4; i++)
#pragma unroll
                for (int h = 0; h < 2; h++)
                    red_row[(wm * 64 + i * 16 + r0 + h * 8) * 4 + wn] = rsum[i][h];
        }
    }

    // Pass 2 (off-diag only): col sums -> red_col
    if (offd) {
        float csum[4][2];
#pragma unroll
        for (int j = 0; j < 4; j++) { csum[j][0] = 0.0f; csum[j][1] = 0.0f; }
#pragma unroll
        for (int i = 0; i < 4; i++)
#pragma unroll
            for (int j = 0; j < 4; j++) {
                csum[j][0] += acc[i][j][0] + acc[i][j][2];
                csum[j][1] += acc[i][j][1] + acc[i][j][3];
            }
#pragma unroll
        for (int j = 0; j < 4; j++)
#pragma unroll
            for (int ec = 0; ec < 2; ec++) {
#pragma unroll
                for (int off = 4; off <= 16; off <<= 1)
                    csum[j][ec] += __shfl_xor_sync(0xffffffffu, csum[j][ec], off);
            }
        if (lid < 4) {
#pragma unroll
            for (int j = 0; j < 4; j++)
#pragma unroll
                for (int ec = 0; ec < 2; ec++)
                    red_col[(wn * 32 + j * 8 + lid * 2 + ec) * 2 + wm] = csum[j][ec];
        }
    }
    __syncthreads();
    if (tid < BM) {
        g_partial[(size_t)(rb + tid) * NCT + jt] =
            red_row[tid * 4] + red_row[tid * 4 + 1]
          + red_row[tid * 4 + 2] + red_row[tid * 4 + 3];
        if (offd)
            g_partial[(size_t)(cb + tid) * NCT + it] =
                red_col[tid * 2] + red_col[tid * 2 + 1];
    }
}

// ---------------------------------------------------------------------------
// Kernel 3: coalesced per-row loss; last block combines deterministically.
// ---------------------------------------------------------------------------
__global__ __launch_bounds__(256) void kfinal(float* __restrict__ out) {
    __shared__ float red[8];
    __shared__ int last;
    const int warp = threadIdx.x >> 5;
    const int lane = threadIdx.x & 31;
    float acc = 0.0f;
#pragma unroll
    for (int rr = 0; rr < 16; rr++) {
        const int row = blockIdx.x * 128 + warp * 16 + rr;
        const float* p = g_partial + (size_t)row * NCT;
        float s = p[lane] + p[lane + 32];
#pragma unroll
        for (int off = 16; off > 0; off >>= 1)
            s += __shfl_xor_sync(0xffffffffu, s, off);
        if (lane == 0) acc += -g_pos[row] * 2.0f + logf(s);
    }
    if (lane == 0) red[warp] = acc;
    __syncthreads();
    if (threadIdx.x == 0) {
        float t = 0.0f;
#pragma unroll
        for (int w = 0; w < 8; w++) t += red[w];
        g_blocksum[blockIdx.x] = t;
        __threadfence();
        last = (atomicAdd(&g_ctr, 1) == FBLK - 1);
    }
    __syncthreads();
    if (last && threadIdx.x == 0) {
        float t = 0.0f;
#pragma unroll
        for (int b = 0; b < FBLK; b++) t += g_blocksum[b];  // fixed order
        out[0] = t / (float)N2;
    }
}

// ---------------------------------------------------------------------------
extern "C" void kernel_launch(void* const* d_in, const int* in_sizes, int n_in,
                              void* d_out, int out_size) {
    const float* xi = (const float*)d_in[0];
    const float* xj = (const float*)d_in[1];
    float* out = (float*)d_out;
    (void)in_sizes; (void)n_in; (void)out_size;

    cudaFuncSetAttribute(kmain_qmma,
                         cudaFuncAttributeMaxDynamicSharedMemorySize, SMEM_BYTES);

    knorm<<<N2 / 8, 256>>>(xi, xj);
    kmain_qmma<<<NTRI, 256, SMEM_BYTES>>>();
    kfinal<<<FBLK, 256>>>(out);
}